// round 1
// baseline (speedup 1.0000x reference)
#include <cuda_runtime.h>
#include <math.h>
#include <stdint.h>

#define BATCH   2
#define SEQ     2048
#define DMODEL  2048
#define NH      32
#define NKVH    8
#define HDIM    64
#define GROUPS  (NH / NKVH)

// ---------------- scratch (static device globals; no allocations) ----------------
__device__ float g_Q[BATCH * SEQ * DMODEL];     // 33.5 MB
__device__ float g_attn[BATCH * SEQ * DMODEL];  // 33.5 MB

// =================================================================================
// Generic GEMM:  C[M,N] = A[M,K] @ W[N,K]^T   (both row-major, K contiguous)
// 128x128 block tile, BK=16, 256 threads, 8x8 per thread.
// kvlayout==1: write C into KV-cache layout [B, KVH, S, HD] (m=b*SEQ+s, n=kvh*64+hd)
// =================================================================================
__global__ __launch_bounds__(256, 2)
void gemm_xwT(const float* __restrict__ A, const float* __restrict__ W,
              float* __restrict__ C, int M, int N, int K, int kvlayout)
{
    const int BK = 16;
    const int LDS = 132;               // padded row stride (floats), mult of 4
    __shared__ float As[BK * LDS];     // As[k][m]
    __shared__ float Ws[BK * LDS];     // Ws[k][n]

    int tid = threadIdx.x;
    int tx = tid & 15;                 // 0..15 -> n groups of 8
    int ty = tid >> 4;                 // 0..15 -> m groups of 8
    int m0 = blockIdx.y * 128;
    int n0 = blockIdx.x * 128;

    float acc[8][8];
#pragma unroll
    for (int i = 0; i < 8; i++)
#pragma unroll
        for (int j = 0; j < 8; j++) acc[i][j] = 0.f;

    const float* Ag = A + (size_t)m0 * K;
    const float* Wg = W + (size_t)n0 * K;

    for (int k0 = 0; k0 < K; k0 += BK) {
#pragma unroll
        for (int q = 0; q < 2; q++) {
            int p = tid + q * 256;     // 0..511
            int r = p >> 2;            // row within tile 0..127
            int c = p & 3;             // float4 index within BK
            float4 av = *(const float4*)(Ag + (size_t)r * K + k0 + c * 4);
            As[(c * 4 + 0) * LDS + r] = av.x;
            As[(c * 4 + 1) * LDS + r] = av.y;
            As[(c * 4 + 2) * LDS + r] = av.z;
            As[(c * 4 + 3) * LDS + r] = av.w;
            float4 wv = *(const float4*)(Wg + (size_t)r * K + k0 + c * 4);
            Ws[(c * 4 + 0) * LDS + r] = wv.x;
            Ws[(c * 4 + 1) * LDS + r] = wv.y;
            Ws[(c * 4 + 2) * LDS + r] = wv.z;
            Ws[(c * 4 + 3) * LDS + r] = wv.w;
        }
        __syncthreads();

#pragma unroll
        for (int kk = 0; kk < BK; kk++) {
            float4 a0 = *(const float4*)&As[kk * LDS + ty * 8];
            float4 a1 = *(const float4*)&As[kk * LDS + ty * 8 + 4];
            float4 b0 = *(const float4*)&Ws[kk * LDS + tx * 8];
            float4 b1 = *(const float4*)&Ws[kk * LDS + tx * 8 + 4];
            float a[8] = {a0.x, a0.y, a0.z, a0.w, a1.x, a1.y, a1.z, a1.w};
            float b[8] = {b0.x, b0.y, b0.z, b0.w, b1.x, b1.y, b1.z, b1.w};
#pragma unroll
            for (int i = 0; i < 8; i++)
#pragma unroll
                for (int j = 0; j < 8; j++)
                    acc[i][j] = fmaf(a[i], b[j], acc[i][j]);
        }
        __syncthreads();
    }

    if (!kvlayout) {
#pragma unroll
        for (int i = 0; i < 8; i++) {
            size_t row = (size_t)(m0 + ty * 8 + i) * N + n0 + tx * 8;
            *(float4*)(C + row)     = make_float4(acc[i][0], acc[i][1], acc[i][2], acc[i][3]);
            *(float4*)(C + row + 4) = make_float4(acc[i][4], acc[i][5], acc[i][6], acc[i][7]);
        }
    } else {
        // m = b*SEQ + s ; n = kvh*64 + hd ; dest [(b*NKVH+kvh)*SEQ + s]*64 + hd
        int n = n0 + tx * 8;
        int kvh = n >> 6;
        int hd  = n & 63;              // 8-wide chunk never crosses 64-boundary
#pragma unroll
        for (int i = 0; i < 8; i++) {
            int m = m0 + ty * 8 + i;
            int b = m >> 11;           // /SEQ
            int s = m & 2047;
            size_t base = (((size_t)b * NKVH + kvh) * SEQ + s) * HDIM + hd;
            *(float4*)(C + base)     = make_float4(acc[i][0], acc[i][1], acc[i][2], acc[i][3]);
            *(float4*)(C + base + 4) = make_float4(acc[i][4], acc[i][5], acc[i][6], acc[i][7]);
        }
    }
}

// =================================================================================
// Flash attention (fp32, causal, GQA). One block = 64 q rows for one (b, h).
// 256 threads as 16x16 grid; each thread owns a 4x4 tile of [m, n] / [m, hd].
// smem: qT[d][m], kT[d][n] (reused as P[m][n]), vs[n][d]  -> 48 KB static.
// =================================================================================
__global__ __launch_bounds__(256)
void attn_kernel(const float* __restrict__ Q, const float* __restrict__ Kc,
                 const float* __restrict__ Vc, float* __restrict__ O)
{
    __shared__ float qT[64 * 64];   // qT[d*64 + m]
    __shared__ float kp[64 * 64];   // kT[d*64 + n], then reused as P[m*64 + n]
    __shared__ float vs[64 * 64];   // vs[n*64 + d]

    int qt = blockIdx.x;            // q tile 0..31
    int h  = blockIdx.y;            // head 0..31
    int b  = blockIdx.z;            // batch
    int tid = threadIdx.x;
    int tx = tid & 15;              // n / hd groups of 4
    int ty = tid >> 4;              // m groups of 4
    int qm0 = qt * 64;
    int kvh = h >> 2;               // GROUPS = 4

    // load Q tile (transposed into qT[d][m])
    const float* qg = Q + ((size_t)(b * SEQ + qm0)) * DMODEL + h * HDIM;
#pragma unroll
    for (int q = 0; q < 4; q++) {
        int p = tid + q * 256;      // 0..1023
        int r = p >> 4;             // q row 0..63
        int c4 = (p & 15) * 4;      // d
        float4 t = *(const float4*)(qg + (size_t)r * DMODEL + c4);
        qT[(c4 + 0) * 64 + r] = t.x;
        qT[(c4 + 1) * 64 + r] = t.y;
        qT[(c4 + 2) * 64 + r] = t.z;
        qT[(c4 + 3) * 64 + r] = t.w;
    }

    float o[4][4];
    float mprev[4], l[4];
#pragma unroll
    for (int i = 0; i < 4; i++) {
        mprev[i] = -1e30f; l[i] = 0.f;
#pragma unroll
        for (int j = 0; j < 4; j++) o[i][j] = 0.f;
    }
    __syncthreads();

    const float* kg0 = Kc + ((size_t)(b * NKVH + kvh)) * SEQ * HDIM;
    const float* vg0 = Vc + ((size_t)(b * NKVH + kvh)) * SEQ * HDIM;

    for (int kt = 0; kt <= qt; kt++) {
        const float* kg = kg0 + kt * 64 * HDIM;
        const float* vg = vg0 + kt * 64 * HDIM;
#pragma unroll
        for (int q = 0; q < 4; q++) {
            int p = tid + q * 256;
            int r = p >> 4;         // key row 0..63
            int c4 = (p & 15) * 4;  // d
            float4 t = *(const float4*)(kg + r * HDIM + c4);
            kp[(c4 + 0) * 64 + r] = t.x;
            kp[(c4 + 1) * 64 + r] = t.y;
            kp[(c4 + 2) * 64 + r] = t.z;
            kp[(c4 + 3) * 64 + r] = t.w;
            float4 u = *(const float4*)(vg + r * HDIM + c4);
            *(float4*)&vs[r * 64 + c4] = u;
        }
        __syncthreads();

        // scores s[4][4] = q . k over d
        float s[4][4];
#pragma unroll
        for (int i = 0; i < 4; i++)
#pragma unroll
            for (int j = 0; j < 4; j++) s[i][j] = 0.f;
#pragma unroll
        for (int d = 0; d < 64; d++) {
            float4 a = *(const float4*)&qT[d * 64 + ty * 4];
            float4 bb = *(const float4*)&kp[d * 64 + tx * 4];
            float av[4] = {a.x, a.y, a.z, a.w};
            float bv[4] = {bb.x, bb.y, bb.z, bb.w};
#pragma unroll
            for (int i = 0; i < 4; i++)
#pragma unroll
                for (int j = 0; j < 4; j++)
                    s[i][j] = fmaf(av[i], bv[j], s[i][j]);
        }

        // scale + causal mask (only the diagonal tile can be partially masked)
        if (kt == qt) {
#pragma unroll
            for (int i = 0; i < 4; i++)
#pragma unroll
                for (int j = 0; j < 4; j++) {
                    float v = s[i][j] * 0.125f;
                    if (tx * 4 + j > ty * 4 + i) v -= 1e9f;
                    s[i][j] = v;
                }
        } else {
#pragma unroll
            for (int i = 0; i < 4; i++)
#pragma unroll
                for (int j = 0; j < 4; j++) s[i][j] *= 0.125f;
        }

        // row max across the 16 tx lanes
        float rm[4];
#pragma unroll
        for (int i = 0; i < 4; i++)
            rm[i] = fmaxf(fmaxf(s[i][0], s[i][1]), fmaxf(s[i][2], s[i][3]));
#pragma unroll
        for (int off = 8; off >= 1; off >>= 1)
#pragma unroll
            for (int i = 0; i < 4; i++)
                rm[i] = fmaxf(rm[i], __shfl_xor_sync(0xffffffffu, rm[i], off));

        float al[4], rs[4];
#pragma unroll
        for (int i = 0; i < 4; i++) {
            float mn = fmaxf(mprev[i], rm[i]);
            al[i] = __expf(mprev[i] - mn);
            mprev[i] = mn;
#pragma unroll
            for (int j = 0; j < 4; j++) s[i][j] = __expf(s[i][j] - mn);
            rs[i] = (s[i][0] + s[i][1]) + (s[i][2] + s[i][3]);
        }
#pragma unroll
        for (int off = 8; off >= 1; off >>= 1)
#pragma unroll
            for (int i = 0; i < 4; i++)
                rs[i] += __shfl_xor_sync(0xffffffffu, rs[i], off);
#pragma unroll
        for (int i = 0; i < 4; i++) {
            l[i] = l[i] * al[i] + rs[i];
#pragma unroll
            for (int j = 0; j < 4; j++) o[i][j] *= al[i];
        }

        __syncthreads();   // everyone done reading kp (scores) before P overwrite
#pragma unroll
        for (int i = 0; i < 4; i++)
            *(float4*)&kp[(ty * 4 + i) * 64 + tx * 4] =
                make_float4(s[i][0], s[i][1], s[i][2], s[i][3]);
        __syncthreads();

        // o[m][hd] += P[m][n] * V[n][hd]
#pragma unroll
        for (int n = 0; n < 64; n++) {
            float4 vv = *(const float4*)&vs[n * 64 + tx * 4];
#pragma unroll
            for (int i = 0; i < 4; i++) {
                float pp = kp[(ty * 4 + i) * 64 + n];
                o[i][0] = fmaf(pp, vv.x, o[i][0]);
                o[i][1] = fmaf(pp, vv.y, o[i][1]);
                o[i][2] = fmaf(pp, vv.z, o[i][2]);
                o[i][3] = fmaf(pp, vv.w, o[i][3]);
            }
        }
        __syncthreads();   // before next tile's loads overwrite kp / vs
    }

    // normalize + store in [b, s, h*64+hd] layout (row-major for the O GEMM)
    float* og = O + ((size_t)(b * SEQ + qm0)) * DMODEL + h * HDIM;
#pragma unroll
    for (int i = 0; i < 4; i++) {
        float inv = 1.f / l[i];
        *(float4*)(og + (size_t)(ty * 4 + i) * DMODEL + tx * 4) =
            make_float4(o[i][0] * inv, o[i][1] * inv, o[i][2] * inv, o[i][3] * inv);
    }
}

// =================================================================================
// launch
// =================================================================================
extern "C" void kernel_launch(void* const* d_in, const int* in_sizes, int n_in,
                              void* d_out, int out_size)
{
    const float* x    = (const float*)d_in[0];
    // d_in[1] = attention_mask: exactly -1e9 * triu(k=1); applied analytically.
    const float* Wq   = (const float*)d_in[2];
    const float* Wk   = (const float*)d_in[3];
    const float* Wv   = (const float*)d_in[4];
    const float* Wo   = (const float*)d_in[5];

    float* out  = (float*)d_out;
    float* Kout = out + (size_t)BATCH * SEQ * DMODEL;                         // 8388608
    float* Vout = Kout + (size_t)BATCH * NKVH * SEQ * HDIM;                   // +2097152

    float *pQ = nullptr, *pA = nullptr;
    cudaGetSymbolAddress((void**)&pQ, g_Q);
    cudaGetSymbolAddress((void**)&pA, g_attn);

    const int M = BATCH * SEQ;   // 4096

    // Q = x @ Wq^T  -> scratch [4096, 2048]
    gemm_xwT<<<dim3(DMODEL / 128, M / 128), 256>>>(x, Wq, pQ, M, DMODEL, DMODEL, 0);
    // K,V = x @ Wk^T / x @ Wv^T -> directly into d_out in [B,KVH,S,HD] layout
    gemm_xwT<<<dim3((NKVH * HDIM) / 128, M / 128), 256>>>(x, Wk, Kout, M, NKVH * HDIM, DMODEL, 1);
    gemm_xwT<<<dim3((NKVH * HDIM) / 128, M / 128), 256>>>(x, Wv, Vout, M, NKVH * HDIM, DMODEL, 1);
    // attention -> scratch [4096, 2048] (already in [b, s, h*hd] order)
    attn_kernel<<<dim3(SEQ / 64, NH, BATCH), 256>>>(pQ, Kout, Vout, pA);
    // output = attn @ Wo^T
    gemm_xwT<<<dim3(DMODEL / 128, M / 128), 256>>>(pA, Wo, out, M, DMODEL, DMODEL, 0);
}

// round 2
// speedup vs baseline: 1.5249x; 1.5249x over previous
#include <cuda_runtime.h>
#include <cuda_bf16.h>
#include <math.h>
#include <stdint.h>

#define BATCH   2
#define SEQ     2048
#define DMODEL  2048
#define NH      32
#define NKVH    8
#define HDIM    64
#define GROUPS  (NH / NKVH)
#define K2      (3 * DMODEL)          // 6144 split-augmented K
#define KVELEMS (BATCH * NKVH * SEQ * HDIM)   // 2097152

// ---------------- scratch (static device globals; no allocations) ----------------
__device__ __align__(256) __nv_bfloat16 g_X2[BATCH * SEQ * K2];        // 50.3 MB (x split; reused for attn split)
__device__ __align__(256) __nv_bfloat16 g_Wq2[DMODEL * K2];            // 25.2 MB
__device__ __align__(256) __nv_bfloat16 g_WkWv2[2 * NKVH * HDIM * K2]; // 12.6 MB (Wk rows 0-511, Wv rows 512-1023)
__device__ __align__(256) __nv_bfloat16 g_Wo2[DMODEL * K2];            // 25.2 MB
__device__ float g_Q[BATCH * SEQ * DMODEL];                            // 33.5 MB
__device__ float g_attn[BATCH * SEQ * DMODEL];                         // 33.5 MB

// =================================================================================
// Split kernels: fp32 -> compensated bf16 pair, folded along K.
// activations: [hi | lo | hi]   weights: [hi | hi | lo]
// =================================================================================
__global__ void split_act(const float* __restrict__ in, __nv_bfloat16* __restrict__ out,
                          int M, int D)
{
    int total = M * D;
    for (int i = blockIdx.x * blockDim.x + threadIdx.x; i < total; i += gridDim.x * blockDim.x) {
        int m = i / D, d = i - m * D;
        float v = in[i];
        __nv_bfloat16 h = __float2bfloat16(v);
        __nv_bfloat16 l = __float2bfloat16(v - __bfloat162float(h));
        size_t base = (size_t)m * (3 * D) + d;
        out[base] = h;
        out[base + D] = l;
        out[base + 2 * D] = h;
    }
}

__global__ void split_wt(const float* __restrict__ in, __nv_bfloat16* __restrict__ out,
                         int M, int D)
{
    int total = M * D;
    for (int i = blockIdx.x * blockDim.x + threadIdx.x; i < total; i += gridDim.x * blockDim.x) {
        int m = i / D, d = i - m * D;
        float v = in[i];
        __nv_bfloat16 h = __float2bfloat16(v);
        __nv_bfloat16 l = __float2bfloat16(v - __bfloat162float(h));
        size_t base = (size_t)m * (3 * D) + d;
        out[base] = h;
        out[base + D] = h;
        out[base + 2 * D] = l;
    }
}

// =================================================================================
// bf16 tensor-core GEMM: C[M,N] = A[M,K2] @ B[N,K2]^T, fp32 accum.
// 128x128 tile, BK=32, 256 threads (8 warps as 2x4), warp tile 64x32,
// mma.m16n8k16, ldmatrix, smem rows padded to 40 bf16 (80B) -> conflict-free LDSM.
// kvmode: scatter C into the KV-cache layout in d_out (n<512 -> K, n>=512 -> V).
// =================================================================================
__device__ __forceinline__ uint32_t smem_u32(const void* p) {
    uint32_t a;
    asm("{ .reg .u64 t; cvta.to.shared.u64 t, %1; cvt.u32.u64 %0, t; }" : "=r"(a) : "l"(p));
    return a;
}

#define LDSM_X4(r0, r1, r2, r3, addr) \
    asm volatile("ldmatrix.sync.aligned.m8n8.x4.shared.b16 {%0,%1,%2,%3}, [%4];" \
                 : "=r"(r0), "=r"(r1), "=r"(r2), "=r"(r3) : "r"(addr))

#define MMA_BF16(c, a, b) \
    asm volatile("mma.sync.aligned.m16n8k16.row.col.f32.bf16.bf16.f32 " \
                 "{%0,%1,%2,%3},{%4,%5,%6,%7},{%8,%9},{%0,%1,%2,%3};" \
                 : "+f"(c[0]), "+f"(c[1]), "+f"(c[2]), "+f"(c[3]) \
                 : "r"(a[0]), "r"(a[1]), "r"(a[2]), "r"(a[3]), "r"(b[0]), "r"(b[1]))

__global__ __launch_bounds__(256)
void gemm_bf16(const __nv_bfloat16* __restrict__ A, const __nv_bfloat16* __restrict__ B,
               float* __restrict__ C, int N, int kvmode)
{
    __shared__ __align__(16) __nv_bfloat16 As[2][128 * 40];
    __shared__ __align__(16) __nv_bfloat16 Bs[2][128 * 40];

    const int tid  = threadIdx.x;
    const int lane = tid & 31;
    const int warp = tid >> 5;
    const int wm = warp >> 2;            // 0..1
    const int wn = warp & 3;             // 0..3
    const int m0 = blockIdx.y * 128;
    const int n0 = blockIdx.x * 128;

    // ldg indexing: 512 uint4 per tile; thread t handles items t, t+256
    const int grow = tid >> 2;           // 0..63
    const int gq   = tid & 3;            // uint4 index within 32-elem row chunk
    const uint4* A4 = reinterpret_cast<const uint4*>(A);
    const uint4* B4 = reinterpret_cast<const uint4*>(B);
    const int rp = K2 / 8;               // uint4 row pitch = 768

    // ldmatrix lane offsets
    const int aml = ((lane >> 3) & 1) * 8 + (lane & 7);
    const int akl = ((lane >> 4) & 1) * 8;
    const int bnl = ((lane >> 4) & 1) * 8 + (lane & 7);
    const int bkl = ((lane >> 3) & 1) * 8;

    const uint32_t as_base = smem_u32(&As[0][0]);
    const uint32_t bs_base = smem_u32(&Bs[0][0]);

    float c[4][4][4];
#pragma unroll
    for (int mi = 0; mi < 4; mi++)
#pragma unroll
        for (int nj = 0; nj < 4; nj++)
#pragma unroll
            for (int e = 0; e < 4; e++) c[mi][nj][e] = 0.f;

    uint4 pa0, pa1, pb0, pb1;
    // preload tile 0
    pa0 = A4[(size_t)(m0 + grow) * rp + gq];
    pa1 = A4[(size_t)(m0 + grow + 64) * rp + gq];
    pb0 = B4[(size_t)(n0 + grow) * rp + gq];
    pb1 = B4[(size_t)(n0 + grow + 64) * rp + gq];
    {
        uint4* d = (uint4*)As[0];
        d[grow * 5 + gq] = pa0;
        d[(grow + 64) * 5 + gq] = pa1;
        uint4* e = (uint4*)Bs[0];
        e[grow * 5 + gq] = pb0;
        e[(grow + 64) * 5 + gq] = pb1;
    }
    __syncthreads();

    const int NT = K2 / 32;              // 192
    for (int t = 0; t < NT; t++) {
        const int buf = t & 1;
        if (t + 1 < NT) {
            int kq = (t + 1) * 4 + gq;
            pa0 = A4[(size_t)(m0 + grow) * rp + kq];
            pa1 = A4[(size_t)(m0 + grow + 64) * rp + kq];
            pb0 = B4[(size_t)(n0 + grow) * rp + kq];
            pb1 = B4[(size_t)(n0 + grow + 64) * rp + kq];
        }

#pragma unroll
        for (int ks = 0; ks < 2; ks++) {
            uint32_t a[4][4], b[4][2];
#pragma unroll
            for (int mi = 0; mi < 4; mi++) {
                uint32_t ad = as_base + buf * 10240u
                            + ((wm * 64 + mi * 16 + aml) * 40 + akl + ks * 16) * 2;
                LDSM_X4(a[mi][0], a[mi][1], a[mi][2], a[mi][3], ad);
            }
#pragma unroll
            for (int nj2 = 0; nj2 < 2; nj2++) {
                uint32_t bd = bs_base + buf * 10240u
                            + ((wn * 32 + nj2 * 16 + bnl) * 40 + bkl + ks * 16) * 2;
                uint32_t r0, r1, r2, r3;
                LDSM_X4(r0, r1, r2, r3, bd);
                b[nj2 * 2][0] = r0; b[nj2 * 2][1] = r1;
                b[nj2 * 2 + 1][0] = r2; b[nj2 * 2 + 1][1] = r3;
            }
#pragma unroll
            for (int mi = 0; mi < 4; mi++)
#pragma unroll
                for (int nj = 0; nj < 4; nj++)
                    MMA_BF16(c[mi][nj], a[mi], b[nj]);
        }

        if (t + 1 < NT) {
            int nbuf = (t + 1) & 1;
            uint4* d = (uint4*)As[nbuf];
            d[grow * 5 + gq] = pa0;
            d[(grow + 64) * 5 + gq] = pa1;
            uint4* e = (uint4*)Bs[nbuf];
            e[grow * 5 + gq] = pb0;
            e[(grow + 64) * 5 + gq] = pb1;
        }
        __syncthreads();
    }

    // epilogue
    const int rbase = (lane >> 2);
    const int cbase = (lane & 3) * 2;
    if (!kvmode) {
#pragma unroll
        for (int mi = 0; mi < 4; mi++) {
#pragma unroll
            for (int nj = 0; nj < 4; nj++) {
                int m = m0 + wm * 64 + mi * 16 + rbase;
                int n = n0 + wn * 32 + nj * 8 + cbase;
                *(float2*)(C + (size_t)m * N + n)       = make_float2(c[mi][nj][0], c[mi][nj][1]);
                *(float2*)(C + (size_t)(m + 8) * N + n) = make_float2(c[mi][nj][2], c[mi][nj][3]);
            }
        }
    } else {
        // n in [0,1024): n<512 -> K cache, else V cache (V base = C + KVELEMS)
#pragma unroll
        for (int mi = 0; mi < 4; mi++) {
#pragma unroll
            for (int nj = 0; nj < 4; nj++) {
                int m = m0 + wm * 64 + mi * 16 + rbase;
                int n = n0 + wn * 32 + nj * 8 + cbase;
                int sel = n >> 9;
                int kvh = (n >> 6) & 7;
                int hd  = n & 63;
                int b   = m >> 11;
                int s   = m & 2047;
                size_t base = (size_t)sel * KVELEMS
                            + (((size_t)b * NKVH + kvh) * SEQ + s) * HDIM + hd;
                *(float2*)(C + base)                    = make_float2(c[mi][nj][0], c[mi][nj][1]);
                *(float2*)(C + base + 8ull * HDIM)      = make_float2(c[mi][nj][2], c[mi][nj][3]);
            }
        }
    }
}

// =================================================================================
// Flash attention (fp32, causal, GQA) — unchanged from round 1.
// =================================================================================
__global__ __launch_bounds__(256)
void attn_kernel(const float* __restrict__ Q, const float* __restrict__ Kc,
                 const float* __restrict__ Vc, float* __restrict__ O)
{
    __shared__ float qT[64 * 64];
    __shared__ float kp[64 * 64];
    __shared__ float vs[64 * 64];

    int qt = blockIdx.x;
    int h  = blockIdx.y;
    int b  = blockIdx.z;
    int tid = threadIdx.x;
    int tx = tid & 15;
    int ty = tid >> 4;
    int qm0 = qt * 64;
    int kvh = h >> 2;

    const float* qg = Q + ((size_t)(b * SEQ + qm0)) * DMODEL + h * HDIM;
#pragma unroll
    for (int q = 0; q < 4; q++) {
        int p = tid + q * 256;
        int r = p >> 4;
        int c4 = (p & 15) * 4;
        float4 t = *(const float4*)(qg + (size_t)r * DMODEL + c4);
        qT[(c4 + 0) * 64 + r] = t.x;
        qT[(c4 + 1) * 64 + r] = t.y;
        qT[(c4 + 2) * 64 + r] = t.z;
        qT[(c4 + 3) * 64 + r] = t.w;
    }

    float o[4][4];
    float mprev[4], l[4];
#pragma unroll
    for (int i = 0; i < 4; i++) {
        mprev[i] = -1e30f; l[i] = 0.f;
#pragma unroll
        for (int j = 0; j < 4; j++) o[i][j] = 0.f;
    }
    __syncthreads();

    const float* kg0 = Kc + ((size_t)(b * NKVH + kvh)) * SEQ * HDIM;
    const float* vg0 = Vc + ((size_t)(b * NKVH + kvh)) * SEQ * HDIM;

    for (int kt = 0; kt <= qt; kt++) {
        const float* kg = kg0 + kt * 64 * HDIM;
        const float* vg = vg0 + kt * 64 * HDIM;
#pragma unroll
        for (int q = 0; q < 4; q++) {
            int p = tid + q * 256;
            int r = p >> 4;
            int c4 = (p & 15) * 4;
            float4 t = *(const float4*)(kg + r * HDIM + c4);
            kp[(c4 + 0) * 64 + r] = t.x;
            kp[(c4 + 1) * 64 + r] = t.y;
            kp[(c4 + 2) * 64 + r] = t.z;
            kp[(c4 + 3) * 64 + r] = t.w;
            float4 u = *(const float4*)(vg + r * HDIM + c4);
            *(float4*)&vs[r * 64 + c4] = u;
        }
        __syncthreads();

        float s[4][4];
#pragma unroll
        for (int i = 0; i < 4; i++)
#pragma unroll
            for (int j = 0; j < 4; j++) s[i][j] = 0.f;
#pragma unroll
        for (int d = 0; d < 64; d++) {
            float4 a = *(const float4*)&qT[d * 64 + ty * 4];
            float4 bb = *(const float4*)&kp[d * 64 + tx * 4];
            float av[4] = {a.x, a.y, a.z, a.w};
            float bv[4] = {bb.x, bb.y, bb.z, bb.w};
#pragma unroll
            for (int i = 0; i < 4; i++)
#pragma unroll
                for (int j = 0; j < 4; j++)
                    s[i][j] = fmaf(av[i], bv[j], s[i][j]);
        }

        if (kt == qt) {
#pragma unroll
            for (int i = 0; i < 4; i++)
#pragma unroll
                for (int j = 0; j < 4; j++) {
                    float v = s[i][j] * 0.125f;
                    if (tx * 4 + j > ty * 4 + i) v -= 1e9f;
                    s[i][j] = v;
                }
        } else {
#pragma unroll
            for (int i = 0; i < 4; i++)
#pragma unroll
                for (int j = 0; j < 4; j++) s[i][j] *= 0.125f;
        }

        float rm[4];
#pragma unroll
        for (int i = 0; i < 4; i++)
            rm[i] = fmaxf(fmaxf(s[i][0], s[i][1]), fmaxf(s[i][2], s[i][3]));
#pragma unroll
        for (int off = 8; off >= 1; off >>= 1)
#pragma unroll
            for (int i = 0; i < 4; i++)
                rm[i] = fmaxf(rm[i], __shfl_xor_sync(0xffffffffu, rm[i], off));

        float al[4], rs[4];
#pragma unroll
        for (int i = 0; i < 4; i++) {
            float mn = fmaxf(mprev[i], rm[i]);
            al[i] = __expf(mprev[i] - mn);
            mprev[i] = mn;
#pragma unroll
            for (int j = 0; j < 4; j++) s[i][j] = __expf(s[i][j] - mn);
            rs[i] = (s[i][0] + s[i][1]) + (s[i][2] + s[i][3]);
        }
#pragma unroll
        for (int off = 8; off >= 1; off >>= 1)
#pragma unroll
            for (int i = 0; i < 4; i++)
                rs[i] += __shfl_xor_sync(0xffffffffu, rs[i], off);
#pragma unroll
        for (int i = 0; i < 4; i++) {
            l[i] = l[i] * al[i] + rs[i];
#pragma unroll
            for (int j = 0; j < 4; j++) o[i][j] *= al[i];
        }

        __syncthreads();
#pragma unroll
        for (int i = 0; i < 4; i++)
            *(float4*)&kp[(ty * 4 + i) * 64 + tx * 4] =
                make_float4(s[i][0], s[i][1], s[i][2], s[i][3]);
        __syncthreads();

#pragma unroll
        for (int n = 0; n < 64; n++) {
            float4 vv = *(const float4*)&vs[n * 64 + tx * 4];
#pragma unroll
            for (int i = 0; i < 4; i++) {
                float pp = kp[(ty * 4 + i) * 64 + n];
                o[i][0] = fmaf(pp, vv.x, o[i][0]);
                o[i][1] = fmaf(pp, vv.y, o[i][1]);
                o[i][2] = fmaf(pp, vv.z, o[i][2]);
                o[i][3] = fmaf(pp, vv.w, o[i][3]);
            }
        }
        __syncthreads();
    }

    float* og = O + ((size_t)(b * SEQ + qm0)) * DMODEL + h * HDIM;
#pragma unroll
    for (int i = 0; i < 4; i++) {
        float inv = 1.f / l[i];
        *(float4*)(og + (size_t)(ty * 4 + i) * DMODEL + tx * 4) =
            make_float4(o[i][0] * inv, o[i][1] * inv, o[i][2] * inv, o[i][3] * inv);
    }
}

// =================================================================================
// launch
// =================================================================================
extern "C" void kernel_launch(void* const* d_in, const int* in_sizes, int n_in,
                              void* d_out, int out_size)
{
    const float* x  = (const float*)d_in[0];
    // d_in[1] = attention_mask: exactly -1e9 * triu(k=1); applied analytically.
    const float* Wq = (const float*)d_in[2];
    const float* Wk = (const float*)d_in[3];
    const float* Wv = (const float*)d_in[4];
    const float* Wo = (const float*)d_in[5];

    float* out  = (float*)d_out;
    float* Kout = out + (size_t)BATCH * SEQ * DMODEL;
    float* Vout = Kout + (size_t)KVELEMS;

    __nv_bfloat16 *pX2, *pWq2, *pWkWv2, *pWo2;
    float *pQ, *pA;
    cudaGetSymbolAddress((void**)&pX2, g_X2);
    cudaGetSymbolAddress((void**)&pWq2, g_Wq2);
    cudaGetSymbolAddress((void**)&pWkWv2, g_WkWv2);
    cudaGetSymbolAddress((void**)&pWo2, g_Wo2);
    cudaGetSymbolAddress((void**)&pQ, g_Q);
    cudaGetSymbolAddress((void**)&pA, g_attn);

    const int M = BATCH * SEQ;   // 4096

    // splits
    split_act<<<2048, 256>>>(x, pX2, M, DMODEL);
    split_wt<<<2048, 256>>>(Wq, pWq2, DMODEL, DMODEL);
    split_wt<<<1024, 256>>>(Wk, pWkWv2, NKVH * HDIM, DMODEL);
    split_wt<<<1024, 256>>>(Wv, pWkWv2 + (size_t)(NKVH * HDIM) * K2, NKVH * HDIM, DMODEL);
    split_wt<<<2048, 256>>>(Wo, pWo2, DMODEL, DMODEL);

    // Q = x @ Wq^T (fp32-accurate via bf16 split)
    gemm_bf16<<<dim3(DMODEL / 128, M / 128), 256>>>(pX2, pWq2, pQ, DMODEL, 0);
    // K,V fused: N=1024, scattered into the cache layout in d_out
    gemm_bf16<<<dim3(1024 / 128, M / 128), 256>>>(pX2, pWkWv2, Kout, 1024, 1);
    // attention (fp32)
    attn_kernel<<<dim3(SEQ / 64, NH, BATCH), 256>>>(pQ, Kout, Vout, pA);
    // split attention output (reuse g_X2), O projection
    split_act<<<2048, 256>>>(pA, pX2, M, DMODEL);
    gemm_bf16<<<dim3(DMODEL / 128, M / 128), 256>>>(pX2, pWo2, out, DMODEL, 0);
}

// round 3
// speedup vs baseline: 2.5022x; 1.6409x over previous
#include <cuda_runtime.h>
#include <cuda_bf16.h>
#include <math.h>
#include <stdint.h>

#define BATCH   2
#define SEQ     2048
#define DMODEL  2048
#define NH      32
#define NKVH    8
#define HDIM    64
#define GROUPS  (NH / NKVH)
#define K2      (3 * DMODEL)                   // 6144 split-augmented K
#define KVELEMS (BATCH * NKVH * SEQ * HDIM)    // 2097152

// ---------------- scratch (static device globals; no allocations) ----------------
__device__ __align__(256) __nv_bfloat16 g_X2[BATCH * SEQ * K2];        // x split; later attn-out split
__device__ __align__(256) __nv_bfloat16 g_Wq2[DMODEL * K2];
__device__ __align__(256) __nv_bfloat16 g_WkWv2[2 * NKVH * HDIM * K2]; // Wk rows 0-511, Wv rows 512-1023
__device__ __align__(256) __nv_bfloat16 g_Wo2[DMODEL * K2];
__device__ __align__(256) __nv_bfloat16 g_Qh[BATCH * NH * SEQ * HDIM];  // [b,h,s,hd]
__device__ __align__(256) __nv_bfloat16 g_Ql[BATCH * NH * SEQ * HDIM];
__device__ __align__(256) __nv_bfloat16 g_Kh[KVELEMS];                  // [b,kvh,s,hd]
__device__ __align__(256) __nv_bfloat16 g_Kl[KVELEMS];
__device__ __align__(256) __nv_bfloat16 g_VTh[KVELEMS];                 // [b,kvh,hd,s]  (transposed)
__device__ __align__(256) __nv_bfloat16 g_VTl[KVELEMS];

// ---------------- helpers ----------------
__device__ __forceinline__ uint32_t smem_u32(const void* p) {
    uint32_t a;
    asm("{ .reg .u64 t; cvta.to.shared.u64 t, %1; cvt.u32.u64 %0, t; }" : "=r"(a) : "l"(p));
    return a;
}

__device__ __forceinline__ void split2(float x, float y, uint32_t& hi, uint32_t& lo) {
    __nv_bfloat16 hx = __float2bfloat16(x), hy = __float2bfloat16(y);
    __nv_bfloat162 h; h.x = hx; h.y = hy;
    __nv_bfloat162 l = __floats2bfloat162_rn(x - __bfloat162float(hx), y - __bfloat162float(hy));
    hi = *(uint32_t*)&h; lo = *(uint32_t*)&l;
}

#define LDSM_X4(r0, r1, r2, r3, addr) \
    asm volatile("ldmatrix.sync.aligned.m8n8.x4.shared.b16 {%0,%1,%2,%3}, [%4];" \
                 : "=r"(r0), "=r"(r1), "=r"(r2), "=r"(r3) : "r"(addr))

#define MMA_BF16(c, a, b) \
    asm volatile("mma.sync.aligned.m16n8k16.row.col.f32.bf16.bf16.f32 " \
                 "{%0,%1,%2,%3},{%4,%5,%6,%7},{%8,%9},{%0,%1,%2,%3};" \
                 : "+f"(c[0]), "+f"(c[1]), "+f"(c[2]), "+f"(c[3]) \
                 : "r"(a[0]), "r"(a[1]), "r"(a[2]), "r"(a[3]), "r"(b[0]), "r"(b[1]))

// =================================================================================
// Split kernels
// =================================================================================
__global__ void split_act(const float* __restrict__ in, __nv_bfloat16* __restrict__ out,
                          int M, int D)
{
    int total = M * D;
    for (int i = blockIdx.x * blockDim.x + threadIdx.x; i < total; i += gridDim.x * blockDim.x) {
        int m = i / D, d = i - m * D;
        float v = in[i];
        __nv_bfloat16 h = __float2bfloat16(v);
        __nv_bfloat16 l = __float2bfloat16(v - __bfloat162float(h));
        size_t base = (size_t)m * (3 * D) + d;
        out[base] = h;
        out[base + D] = l;
        out[base + 2 * D] = h;
    }
}

__global__ void split_wt(const float* __restrict__ in, __nv_bfloat16* __restrict__ out,
                         int M, int D)
{
    int total = M * D;
    for (int i = blockIdx.x * blockDim.x + threadIdx.x; i < total; i += gridDim.x * blockDim.x) {
        int m = i / D, d = i - m * D;
        float v = in[i];
        __nv_bfloat16 h = __float2bfloat16(v);
        __nv_bfloat16 l = __float2bfloat16(v - __bfloat162float(h));
        size_t base = (size_t)m * (3 * D) + d;
        out[base] = h;
        out[base + D] = h;
        out[base + 2 * D] = l;
    }
}

// =================================================================================
// bf16 tensor-core GEMM: C[M,N] = A[M,K2] @ B[N,K2]^T, fp32 accum.
// mode 0: plain fp32 C.   mode 1: KV (fp32 caches + split K + split V^T).
// mode 2: Q (split bf16 into g_Qh/g_Ql, no fp32).
// =================================================================================
__global__ __launch_bounds__(256)
void gemm_bf16(const __nv_bfloat16* __restrict__ A, const __nv_bfloat16* __restrict__ B,
               float* __restrict__ C, int N, int mode)
{
    __shared__ __align__(16) __nv_bfloat16 As[2][128 * 40];
    __shared__ __align__(16) __nv_bfloat16 Bs[2][128 * 40];

    const int tid  = threadIdx.x;
    const int lane = tid & 31;
    const int warp = tid >> 5;
    const int wm = warp >> 2;
    const int wn = warp & 3;
    const int m0 = blockIdx.y * 128;
    const int n0 = blockIdx.x * 128;

    const int grow = tid >> 2;
    const int gq   = tid & 3;
    const uint4* A4 = reinterpret_cast<const uint4*>(A);
    const uint4* B4 = reinterpret_cast<const uint4*>(B);
    const int rp = K2 / 8;

    const int aml = ((lane >> 3) & 1) * 8 + (lane & 7);
    const int akl = ((lane >> 4) & 1) * 8;
    const int bnl = ((lane >> 4) & 1) * 8 + (lane & 7);
    const int bkl = ((lane >> 3) & 1) * 8;

    const uint32_t as_base = smem_u32(&As[0][0]);
    const uint32_t bs_base = smem_u32(&Bs[0][0]);

    float c[4][4][4];
#pragma unroll
    for (int mi = 0; mi < 4; mi++)
#pragma unroll
        for (int nj = 0; nj < 4; nj++)
#pragma unroll
            for (int e = 0; e < 4; e++) c[mi][nj][e] = 0.f;

    uint4 pa0, pa1, pb0, pb1;
    pa0 = A4[(size_t)(m0 + grow) * rp + gq];
    pa1 = A4[(size_t)(m0 + grow + 64) * rp + gq];
    pb0 = B4[(size_t)(n0 + grow) * rp + gq];
    pb1 = B4[(size_t)(n0 + grow + 64) * rp + gq];
    {
        uint4* d = (uint4*)As[0];
        d[grow * 5 + gq] = pa0;
        d[(grow + 64) * 5 + gq] = pa1;
        uint4* e = (uint4*)Bs[0];
        e[grow * 5 + gq] = pb0;
        e[(grow + 64) * 5 + gq] = pb1;
    }
    __syncthreads();

    const int NT = K2 / 32;
    for (int t = 0; t < NT; t++) {
        const int buf = t & 1;
        if (t + 1 < NT) {
            int kq = (t + 1) * 4 + gq;
            pa0 = A4[(size_t)(m0 + grow) * rp + kq];
            pa1 = A4[(size_t)(m0 + grow + 64) * rp + kq];
            pb0 = B4[(size_t)(n0 + grow) * rp + kq];
            pb1 = B4[(size_t)(n0 + grow + 64) * rp + kq];
        }

#pragma unroll
        for (int ks = 0; ks < 2; ks++) {
            uint32_t a[4][4], b[4][2];
#pragma unroll
            for (int mi = 0; mi < 4; mi++) {
                uint32_t ad = as_base + buf * 10240u
                            + ((wm * 64 + mi * 16 + aml) * 40 + akl + ks * 16) * 2;
                LDSM_X4(a[mi][0], a[mi][1], a[mi][2], a[mi][3], ad);
            }
#pragma unroll
            for (int nj2 = 0; nj2 < 2; nj2++) {
                uint32_t bd = bs_base + buf * 10240u
                            + ((wn * 32 + nj2 * 16 + bnl) * 40 + bkl + ks * 16) * 2;
                uint32_t r0, r1, r2, r3;
                LDSM_X4(r0, r1, r2, r3, bd);
                b[nj2 * 2][0] = r0; b[nj2 * 2][1] = r1;
                b[nj2 * 2 + 1][0] = r2; b[nj2 * 2 + 1][1] = r3;
            }
#pragma unroll
            for (int mi = 0; mi < 4; mi++)
#pragma unroll
                for (int nj = 0; nj < 4; nj++)
                    MMA_BF16(c[mi][nj], a[mi], b[nj]);
        }

        if (t + 1 < NT) {
            int nbuf = (t + 1) & 1;
            uint4* d = (uint4*)As[nbuf];
            d[grow * 5 + gq] = pa0;
            d[(grow + 64) * 5 + gq] = pa1;
            uint4* e = (uint4*)Bs[nbuf];
            e[grow * 5 + gq] = pb0;
            e[(grow + 64) * 5 + gq] = pb1;
        }
        __syncthreads();
    }

    const int rbase = (lane >> 2);
    const int cbase = (lane & 3) * 2;
    if (mode == 0) {
#pragma unroll
        for (int mi = 0; mi < 4; mi++)
#pragma unroll
            for (int nj = 0; nj < 4; nj++) {
                int m = m0 + wm * 64 + mi * 16 + rbase;
                int n = n0 + wn * 32 + nj * 8 + cbase;
                *(float2*)(C + (size_t)m * N + n)       = make_float2(c[mi][nj][0], c[mi][nj][1]);
                *(float2*)(C + (size_t)(m + 8) * N + n) = make_float2(c[mi][nj][2], c[mi][nj][3]);
            }
    } else if (mode == 1) {
#pragma unroll
        for (int mi = 0; mi < 4; mi++)
#pragma unroll
            for (int nj = 0; nj < 4; nj++) {
                int m = m0 + wm * 64 + mi * 16 + rbase;
                int n = n0 + wn * 32 + nj * 8 + cbase;
                int sel = n >> 9;
                int kvh = (n >> 6) & 7;
                int hd  = n & 63;
                int bb  = m >> 11;
                int sq  = m & 2047;
                size_t cb = (((size_t)bb * NKVH + kvh) * SEQ + sq) * HDIM + hd;
                float v0 = c[mi][nj][0], v1 = c[mi][nj][1];
                float v2 = c[mi][nj][2], v3 = c[mi][nj][3];
                *(float2*)(C + (size_t)sel * KVELEMS + cb)              = make_float2(v0, v1);
                *(float2*)(C + (size_t)sel * KVELEMS + cb + 8 * HDIM)   = make_float2(v2, v3);
                if (sel == 0) {
                    uint32_t h2, l2;
                    split2(v0, v1, h2, l2);
                    *(uint32_t*)&g_Kh[cb] = h2; *(uint32_t*)&g_Kl[cb] = l2;
                    split2(v2, v3, h2, l2);
                    *(uint32_t*)&g_Kh[cb + 8 * HDIM] = h2; *(uint32_t*)&g_Kl[cb + 8 * HDIM] = l2;
                } else {
                    size_t vt = (((size_t)bb * NKVH + kvh) * HDIM + hd) * SEQ + sq;
                    __nv_bfloat16 h;
                    h = __float2bfloat16(v0); g_VTh[vt]           = h; g_VTl[vt]           = __float2bfloat16(v0 - __bfloat162float(h));
                    h = __float2bfloat16(v1); g_VTh[vt + SEQ]     = h; g_VTl[vt + SEQ]     = __float2bfloat16(v1 - __bfloat162float(h));
                    h = __float2bfloat16(v2); g_VTh[vt + 8]       = h; g_VTl[vt + 8]       = __float2bfloat16(v2 - __bfloat162float(h));
                    h = __float2bfloat16(v3); g_VTh[vt + SEQ + 8] = h; g_VTl[vt + SEQ + 8] = __float2bfloat16(v3 - __bfloat162float(h));
                }
            }
    } else {   // mode 2: Q split
#pragma unroll
        for (int mi = 0; mi < 4; mi++)
#pragma unroll
            for (int nj = 0; nj < 4; nj++) {
                int m = m0 + wm * 64 + mi * 16 + rbase;
                int n = n0 + wn * 32 + nj * 8 + cbase;
                int h  = n >> 6;
                int hd = n & 63;
                int bb = m >> 11;
                int sq = m & 2047;
                size_t qb = (((size_t)bb * NH + h) * SEQ + sq) * HDIM + hd;
                uint32_t h2, l2;
                split2(c[mi][nj][0], c[mi][nj][1], h2, l2);
                *(uint32_t*)&g_Qh[qb] = h2; *(uint32_t*)&g_Ql[qb] = l2;
                split2(c[mi][nj][2], c[mi][nj][3], h2, l2);
                *(uint32_t*)&g_Qh[qb + 8 * HDIM] = h2; *(uint32_t*)&g_Ql[qb + 8 * HDIM] = l2;
            }
    }
}

// =================================================================================
// Tensor-core flash attention (split-bf16, fp32 accum, causal, GQA).
// Block: 128 q-rows x 1 head. 8 warps x 16 rows. 64-key tiles.
// Output written pre-split into g_X2 ([hi | lo | hi] along K2) for the O gemm.
// =================================================================================
__global__ __launch_bounds__(256)
void attn_tc()
{
    extern __shared__ __nv_bfloat16 sm[];
    __nv_bfloat16* qh = sm;             // [128][72]
    __nv_bfloat16* ql = sm + 9216;
    __nv_bfloat16* kh = sm + 18432;     // [64][72]
    __nv_bfloat16* kl = sm + 23040;
    __nv_bfloat16* vh = sm + 27648;     // [64][72]  (V^T: rows=d, cols=key)
    __nv_bfloat16* vl = sm + 32256;

    const int qt = blockIdx.x;
    const int h  = blockIdx.y;
    const int b  = blockIdx.z;
    const int tid = threadIdx.x;
    const int lane = tid & 31;
    const int w = tid >> 5;
    const int kvh = h >> 2;

    // load Q tile (hi+lo)
    {
        size_t qb4 = ((size_t)(b * NH + h) * SEQ + qt * 128) * 8;
        uint4* qh4 = (uint4*)qh;
        uint4* ql4 = (uint4*)ql;
        const uint4* gqh = (const uint4*)g_Qh;
        const uint4* gql = (const uint4*)g_Ql;
#pragma unroll
        for (int i = tid; i < 1024; i += 256) {
            int r = i >> 3, cc = i & 7;
            qh4[r * 9 + cc] = gqh[qb4 + r * 8 + cc];
            ql4[r * 9 + cc] = gql[qb4 + r * 8 + cc];
        }
    }

    const int aml = ((lane >> 3) & 1) * 8 + (lane & 7);
    const int akl = ((lane >> 4) & 1) * 8;
    const int bnl = ((lane >> 4) & 1) * 8 + (lane & 7);
    const int bkl = ((lane >> 3) & 1) * 8;

    const uint32_t qhb = smem_u32(qh), qlb = smem_u32(ql);
    const uint32_t khb = smem_u32(kh), klb = smem_u32(kl);
    const uint32_t vhb = smem_u32(vh), vlb = smem_u32(vl);

    float o[8][4];
#pragma unroll
    for (int nt = 0; nt < 8; nt++)
#pragma unroll
        for (int e = 0; e < 4; e++) o[nt][e] = 0.f;
    float mp0 = -1e30f, mp1 = -1e30f, l0 = 0.f, l1 = 0.f;

    const size_t kvb = (size_t)b * NKVH + kvh;
    const int ktmax = 2 * qt + 1;

    for (int kt = 0; kt <= ktmax; kt++) {
        __syncthreads();
        {
            uint4* kh4 = (uint4*)kh; uint4* kl4 = (uint4*)kl;
            uint4* vh4 = (uint4*)vh; uint4* vl4 = (uint4*)vl;
            const uint4* gkh = (const uint4*)g_Kh;
            const uint4* gkl = (const uint4*)g_Kl;
            const uint4* gvh = (const uint4*)g_VTh;
            const uint4* gvl = (const uint4*)g_VTl;
#pragma unroll
            for (int i = tid; i < 512; i += 256) {
                int r = i >> 3, cc = i & 7;
                size_t gk = (kvb * SEQ + kt * 64 + r) * 8 + cc;
                kh4[r * 9 + cc] = gkh[gk];
                kl4[r * 9 + cc] = gkl[gk];
                size_t gv = (kvb * 64 + r) * (SEQ / 8) + kt * 8 + cc;
                vh4[r * 9 + cc] = gvh[gv];
                vl4[r * 9 + cc] = gvl[gv];
            }
        }
        __syncthreads();

        // ---- scores = Q K^T (split bf16) ----
        float s[8][4];
#pragma unroll
        for (int nt = 0; nt < 8; nt++)
#pragma unroll
            for (int e = 0; e < 4; e++) s[nt][e] = 0.f;

#pragma unroll
        for (int kc = 0; kc < 4; kc++) {
            uint32_t ah[4], alo[4];
            uint32_t aoff = ((w * 16 + aml) * 72 + kc * 16 + akl) * 2;
            LDSM_X4(ah[0], ah[1], ah[2], ah[3], qhb + aoff);
            LDSM_X4(alo[0], alo[1], alo[2], alo[3], qlb + aoff);
#pragma unroll
            for (int nt2 = 0; nt2 < 4; nt2++) {
                uint32_t bh[4], bl[4];
                uint32_t boff = ((nt2 * 16 + bnl) * 72 + kc * 16 + bkl) * 2;
                LDSM_X4(bh[0], bh[1], bh[2], bh[3], khb + boff);
                LDSM_X4(bl[0], bl[1], bl[2], bl[3], klb + boff);
                uint32_t b0h[2] = {bh[0], bh[1]}, b1h[2] = {bh[2], bh[3]};
                uint32_t b0l[2] = {bl[0], bl[1]}, b1l[2] = {bl[2], bl[3]};
                MMA_BF16(s[nt2 * 2],     ah,  b0h);
                MMA_BF16(s[nt2 * 2 + 1], ah,  b1h);
                MMA_BF16(s[nt2 * 2],     alo, b0h);
                MMA_BF16(s[nt2 * 2 + 1], alo, b1h);
                MMA_BF16(s[nt2 * 2],     ah,  b0l);
                MMA_BF16(s[nt2 * 2 + 1], ah,  b1l);
            }
        }

        // ---- scale + causal mask ----
        const int qr0 = qt * 128 + w * 16 + (lane >> 2);
        if (kt * 64 + 63 > qt * 128 + w * 16) {
#pragma unroll
            for (int nt = 0; nt < 8; nt++) {
#pragma unroll
                for (int e = 0; e < 4; e++) {
                    int key = kt * 64 + nt * 8 + (lane & 3) * 2 + (e & 1);
                    int row = (e < 2) ? qr0 : qr0 + 8;
                    s[nt][e] = (key > row) ? -1e30f : s[nt][e] * 0.125f;
                }
            }
        } else {
#pragma unroll
            for (int nt = 0; nt < 8; nt++)
#pragma unroll
                for (int e = 0; e < 4; e++) s[nt][e] *= 0.125f;
        }

        // ---- online softmax ----
        float rm0 = -1e30f, rm1 = -1e30f;
#pragma unroll
        for (int nt = 0; nt < 8; nt++) {
            rm0 = fmaxf(rm0, fmaxf(s[nt][0], s[nt][1]));
            rm1 = fmaxf(rm1, fmaxf(s[nt][2], s[nt][3]));
        }
        rm0 = fmaxf(rm0, __shfl_xor_sync(0xffffffffu, rm0, 1));
        rm0 = fmaxf(rm0, __shfl_xor_sync(0xffffffffu, rm0, 2));
        rm1 = fmaxf(rm1, __shfl_xor_sync(0xffffffffu, rm1, 1));
        rm1 = fmaxf(rm1, __shfl_xor_sync(0xffffffffu, rm1, 2));

        float mn0 = fmaxf(mp0, rm0), mn1 = fmaxf(mp1, rm1);
        float al0 = __expf(mp0 - mn0), al1 = __expf(mp1 - mn1);
        mp0 = mn0; mp1 = mn1;

        float rs0 = 0.f, rs1 = 0.f;
#pragma unroll
        for (int nt = 0; nt < 8; nt++) {
            s[nt][0] = __expf(s[nt][0] - mn0);
            s[nt][1] = __expf(s[nt][1] - mn0);
            s[nt][2] = __expf(s[nt][2] - mn1);
            s[nt][3] = __expf(s[nt][3] - mn1);
            rs0 += s[nt][0] + s[nt][1];
            rs1 += s[nt][2] + s[nt][3];
        }
        rs0 += __shfl_xor_sync(0xffffffffu, rs0, 1);
        rs0 += __shfl_xor_sync(0xffffffffu, rs0, 2);
        rs1 += __shfl_xor_sync(0xffffffffu, rs1, 1);
        rs1 += __shfl_xor_sync(0xffffffffu, rs1, 2);
        l0 = l0 * al0 + rs0;
        l1 = l1 * al1 + rs1;
#pragma unroll
        for (int nt = 0; nt < 8; nt++) {
            o[nt][0] *= al0; o[nt][1] *= al0;
            o[nt][2] *= al1; o[nt][3] *= al1;
        }

        // ---- o += P V (split bf16; P split from fp32 fragments) ----
#pragma unroll
        for (int kc = 0; kc < 4; kc++) {
            uint32_t ph[4], pl[4];
            split2(s[2 * kc][0],     s[2 * kc][1],     ph[0], pl[0]);
            split2(s[2 * kc][2],     s[2 * kc][3],     ph[1], pl[1]);
            split2(s[2 * kc + 1][0], s[2 * kc + 1][1], ph[2], pl[2]);
            split2(s[2 * kc + 1][2], s[2 * kc + 1][3], ph[3], pl[3]);
#pragma unroll
            for (int nt2 = 0; nt2 < 4; nt2++) {
                uint32_t bh[4], bl[4];
                uint32_t boff = ((nt2 * 16 + bnl) * 72 + kc * 16 + bkl) * 2;
                LDSM_X4(bh[0], bh[1], bh[2], bh[3], vhb + boff);
                LDSM_X4(bl[0], bl[1], bl[2], bl[3], vlb + boff);
                uint32_t b0h[2] = {bh[0], bh[1]}, b1h[2] = {bh[2], bh[3]};
                uint32_t b0l[2] = {bl[0], bl[1]}, b1l[2] = {bl[2], bl[3]};
                MMA_BF16(o[nt2 * 2],     ph, b0h);
                MMA_BF16(o[nt2 * 2 + 1], ph, b1h);
                MMA_BF16(o[nt2 * 2],     pl, b0h);
                MMA_BF16(o[nt2 * 2 + 1], pl, b1h);
                MMA_BF16(o[nt2 * 2],     ph, b0l);
                MMA_BF16(o[nt2 * 2 + 1], ph, b1l);
            }
        }
    }

    // ---- epilogue: normalize + write pre-split into g_X2 ----
    float inv0 = 1.f / l0, inv1 = 1.f / l1;
    int mrow = b * SEQ + qt * 128 + w * 16 + (lane >> 2);
#pragma unroll
    for (int nt = 0; nt < 8; nt++) {
        int col = h * 64 + nt * 8 + (lane & 3) * 2;
        uint32_t h2, l2;
        size_t r0o = (size_t)mrow * K2 + col;
        split2(o[nt][0] * inv0, o[nt][1] * inv0, h2, l2);
        *(uint32_t*)&g_X2[r0o]              = h2;
        *(uint32_t*)&g_X2[r0o + DMODEL]     = l2;
        *(uint32_t*)&g_X2[r0o + 2 * DMODEL] = h2;
        size_t r1o = r0o + (size_t)8 * K2;
        split2(o[nt][2] * inv1, o[nt][3] * inv1, h2, l2);
        *(uint32_t*)&g_X2[r1o]              = h2;
        *(uint32_t*)&g_X2[r1o + DMODEL]     = l2;
        *(uint32_t*)&g_X2[r1o + 2 * DMODEL] = h2;
    }
}

// =================================================================================
// launch
// =================================================================================
extern "C" void kernel_launch(void* const* d_in, const int* in_sizes, int n_in,
                              void* d_out, int out_size)
{
    const float* x  = (const float*)d_in[0];
    // d_in[1] = attention_mask: exactly -1e9 * triu(k=1); applied analytically.
    const float* Wq = (const float*)d_in[2];
    const float* Wk = (const float*)d_in[3];
    const float* Wv = (const float*)d_in[4];
    const float* Wo = (const float*)d_in[5];

    float* out  = (float*)d_out;
    float* Kout = out + (size_t)BATCH * SEQ * DMODEL;

    __nv_bfloat16 *pX2, *pWq2, *pWkWv2, *pWo2;
    cudaGetSymbolAddress((void**)&pX2, g_X2);
    cudaGetSymbolAddress((void**)&pWq2, g_Wq2);
    cudaGetSymbolAddress((void**)&pWkWv2, g_WkWv2);
    cudaGetSymbolAddress((void**)&pWo2, g_Wo2);

    static bool attr_set = false;
    if (!attr_set) {
        cudaFuncSetAttribute(attn_tc, cudaFuncAttributeMaxDynamicSharedMemorySize, 73728);
        attr_set = true;
    }

    const int M = BATCH * SEQ;   // 4096

    split_act<<<2048, 256>>>(x, pX2, M, DMODEL);
    split_wt<<<2048, 256>>>(Wq, pWq2, DMODEL, DMODEL);
    split_wt<<<1024, 256>>>(Wk, pWkWv2, NKVH * HDIM, DMODEL);
    split_wt<<<1024, 256>>>(Wv, pWkWv2 + (size_t)(NKVH * HDIM) * K2, NKVH * HDIM, DMODEL);
    split_wt<<<2048, 256>>>(Wo, pWo2, DMODEL, DMODEL);

    // Q projection -> split bf16 Q (no fp32 round-trip)
    gemm_bf16<<<dim3(DMODEL / 128, M / 128), 256>>>(pX2, pWq2, nullptr, DMODEL, 2);
    // K,V projection -> fp32 caches in d_out + split K + split V^T
    gemm_bf16<<<dim3(1024 / 128, M / 128), 256>>>(pX2, pWkWv2, Kout, 1024, 1);
    // tensor-core flash attention -> writes pre-split output into g_X2
    attn_tc<<<dim3(SEQ / 128, NH, BATCH), 256, 73728>>>();
    // O projection
    gemm_bf16<<<dim3(DMODEL / 128, M / 128), 256>>>(pX2, pWo2, out, DMODEL, 0);
}